// round 6
// baseline (speedup 1.0000x reference)
#include <cuda_runtime.h>
#include <math.h>

#define BATCH 2
#define SEQ   4096
#define EMB   512
#define DQ    64
#define NC    129
#define ZCONST 3967.0f

typedef unsigned long long ull;

// ---- scratch (allocation-free: device globals) ----
__device__ float g_Q[BATCH * SEQ * DQ];
__device__ float g_K[BATCH * SEQ * DQ];
__device__ float g_Vc[BATCH * NC * DQ];
__device__ float g_part[BATCH * 64 * EMB];
__device__ float g_vtp[BATCH * 8 * DQ];
__device__ float4 g_Wp[DQ * 256];   // [d][kp]: {wq[2kp],wq[2kp+1],wk[2kp],wk[2kp+1]}

__device__ __forceinline__ void ffma2(ull& acc, ull a, ull b) {
    asm("fma.rn.f32x2 %0, %1, %2, %0;" : "+l"(acc) : "l"(a), "l"(b));
}

// ============================================================
// Kernel A (prep): 514 blocks x 128 threads.
//  blocks [0,128):    pack W into g_Wp
//  blocks [128,256):  xsum partials over rows 129..4095
//  blocks [256,514):  V projection rows 0..128
// ============================================================
__global__ void __launch_bounds__(128)
prep_kernel(const float* __restrict__ x,
            const float* __restrict__ Wq, const float* __restrict__ Wk,
            const float* __restrict__ Wv, const float* __restrict__ bv) {
    const int bid = blockIdx.x, t = threadIdx.x;

    if (bid < 128) {                 // ---- pack W ----
        const int kp = bid * 2 + (t >> 6);
        const int d  = t & 63;
        float4 w;
        w.x = Wq[(size_t)(2 * kp)     * DQ + d];
        w.y = Wq[(size_t)(2 * kp + 1) * DQ + d];
        w.z = Wk[(size_t)(2 * kp)     * DQ + d];
        w.w = Wk[(size_t)(2 * kp + 1) * DQ + d];
        g_Wp[d * 256 + kp] = w;
    } else if (bid < 256) {          // ---- xsum partials ----
        const int i = bid - 128;
        const int b = i >> 6, ci = i & 63;
        int r0 = 129 + ci * 62;
        int r1 = r0 + 62; if (r1 > SEQ) r1 = SEQ;
        const float* xb = x + (size_t)b * SEQ * EMB;
        float4 s = make_float4(0.f, 0.f, 0.f, 0.f);
#pragma unroll 4
        for (int r = r0; r < r1; r++) {
            float4 v = *(const float4*)(xb + (size_t)r * EMB + t * 4);
            s.x += v.x; s.y += v.y; s.z += v.z; s.w += v.w;
        }
        *(float4*)(g_part + (b * 64 + ci) * EMB + t * 4) = s;
    } else {                         // ---- V head projection ----
        const int i = bid - 256;           // 0..257
        const int b = i / NC, r = i % NC;
        __shared__ float xsh[EMB];
        __shared__ float red[2][DQ];
        const float* xr = x + ((size_t)b * SEQ + r) * EMB;
        ((float4*)xsh)[t] = ((const float4*)xr)[t];
        __syncthreads();
        const int d = t & 63, h = t >> 6;
        float acc = 0.f;
        const int kb = h * 256;
#pragma unroll 8
        for (int k = 0; k < 256; k++)
            acc = fmaf(xsh[kb + k], Wv[(size_t)(kb + k) * DQ + d], acc);
        red[h][d] = acc;
        __syncthreads();
        if (t < DQ)
            g_Vc[(b * NC + r) * DQ + t] = red[0][t] + red[1][t] + bv[t];
    }
}

// ============================================================
// Kernel B: vtail partials per k-group: grid (8, 2), 256 threads.
// ============================================================
__global__ void vtail_combine_kernel(const float* __restrict__ Wv) {
    const int kg = blockIdx.x, b = blockIdx.y, t = threadIdx.x;
    __shared__ float red[4][DQ];
    __shared__ float xsum64[DQ];
    __shared__ float p2[4][DQ];
    {
        const int kk = t & 63, g = t >> 6;
        float s = 0.f;
#pragma unroll
        for (int ci = g; ci < 64; ci += 4)
            s += g_part[(b * 64 + ci) * EMB + kg * 64 + kk];
        red[g][kk] = s;
    }
    __syncthreads();
    if (t < DQ) xsum64[t] = red[0][t] + red[1][t] + red[2][t] + red[3][t];
    __syncthreads();
    {
        const int d = t & 63, g2 = t >> 6;
        float acc = 0.f;
#pragma unroll
        for (int kk = g2 * 16; kk < g2 * 16 + 16; kk++)
            acc = fmaf(xsum64[kk], Wv[(size_t)(kg * 64 + kk) * DQ + d], acc);
        p2[g2][d] = acc;
    }
    __syncthreads();
    if (t < DQ)
        g_vtp[(b * 8 + kg) * DQ + t] = p2[0][t] + p2[1][t] + p2[2][t] + p2[3][t];
}

// ============================================================
// Kernel C: Q/K projection. 32-row tiles, grid (128,2), 256 thr, 2 blocks/SM.
// Inner: 8 broadcast LDS.64 (x-pairs) + 1 LDG.128 (packed W) + 16 FFMA2.
// ============================================================
__global__ void __launch_bounds__(256, 2)
proj_qk_kernel(const float* __restrict__ x,
               const float* __restrict__ bq, const float* __restrict__ bk) {
    __shared__ float xs[32][130];
    const int b  = blockIdx.y;
    const int n0 = blockIdx.x * 32;
    const int t  = threadIdx.x;
    const int d  = t & 63;
    const int rg = t >> 6;           // 4 groups x 8 rows

    ull qa[8], ka[8];
#pragma unroll
    for (int i = 0; i < 8; i++) { qa[i] = 0ull; ka[i] = 0ull; }

    const float* xb = x + ((size_t)b * SEQ + n0) * EMB;
    const ulonglong2* wp = (const ulonglong2*)g_Wp + (size_t)d * 256;

    for (int k0 = 0; k0 < EMB; k0 += 128) {
        __syncthreads();
        for (int idx = t; idx < 32 * 32; idx += 256) {
            int r = idx >> 5, c4 = idx & 31;
            float4 v = *(const float4*)(xb + (size_t)r * EMB + k0 + c4 * 4);
            float* p = &xs[r][c4 * 4];
            p[0] = v.x; p[1] = v.y; p[2] = v.z; p[3] = v.w;
        }
        __syncthreads();

        const int kpb = k0 >> 1;
#pragma unroll 8
        for (int kp = 0; kp < 64; kp++) {
            ulonglong2 w = wp[kpb + kp];
#pragma unroll
            for (int i = 0; i < 8; i++) {
                ull x2 = *(const ull*)(&xs[rg * 8 + i][kp * 2]);
                ffma2(qa[i], x2, w.x);
                ffma2(ka[i], x2, w.y);
            }
        }
    }

    float bqv = bq[d], bkv = bk[d];
#pragma unroll
    for (int i = 0; i < 8; i++) {
        int n = n0 + rg * 8 + i;
        float q = __uint_as_float((unsigned)qa[i]) + __uint_as_float((unsigned)(qa[i] >> 32)) + bqv;
        float k = __uint_as_float((unsigned)ka[i]) + __uint_as_float((unsigned)(ka[i] >> 32)) + bkv;
        g_Q[((size_t)b * SEQ + n) * DQ + d] = q;
        g_K[((size_t)b * SEQ + n) * DQ + d] = k;
    }
}

// ============================================================
// Kernel D: attention core, FFMA2 in both GEMM phases.
// ============================================================
#define KS_PITCH 66
#define ES_PITCH 130
#define SM_KS  0
#define SM_QS  (192 * KS_PITCH)
#define SM_ES  (SM_QS + 64 * KS_PITCH)
#define SM_VST (SM_ES + 64 * ES_PITCH)
#define SM_ZI  (SM_VST + 64 * ES_PITCH)
#define SM_VT  (SM_ZI + 64)
#define SM_FLOATS (SM_VT + 64)
#define SM_BYTES (SM_FLOATS * 4)

__global__ void __launch_bounds__(256, 1)
attn_kernel(float* __restrict__ out, const float* __restrict__ bv) {
    extern __shared__ float sm[];
    float* Ks  = sm + SM_KS;
    float* Qs  = sm + SM_QS;
    float* Es  = sm + SM_ES;
    float* Vst = sm + SM_VST;
    float* Zi  = sm + SM_ZI;
    float* Vt  = sm + SM_VT;

    const int b = blockIdx.y, n0 = blockIdx.x * 64, t = threadIdx.x;

    const float* Kb = g_K + (size_t)b * SEQ * DQ;
    for (int idx = t; idx < 192 * 16; idx += 256) {
        int r = idx >> 4, c4 = idx & 15;
        int j = n0 - 64 + r;
        float4 v = (j >= 0 && j < SEQ) ? *(const float4*)(Kb + (size_t)j * DQ + c4 * 4)
                                       : make_float4(0.f, 0.f, 0.f, 0.f);
        float* p = Ks + r * KS_PITCH + c4 * 4;
        p[0] = v.x; p[1] = v.y; p[2] = v.z; p[3] = v.w;
    }
    const float* Qb = g_Q + ((size_t)b * SEQ + n0) * DQ;
    for (int idx = t; idx < 64 * 16; idx += 256) {
        int r = idx >> 4, c4 = idx & 15;
        float4 v = *(const float4*)(Qb + (size_t)r * DQ + c4 * 4);
        float* p = Qs + r * KS_PITCH + c4 * 4;
        p[0] = v.x; p[1] = v.y; p[2] = v.z; p[3] = v.w;
    }
    for (int idx = t; idx < NC * 16; idx += 256) {
        int r = idx >> 4, c4 = idx & 15;
        float4 v = *(const float4*)(g_Vc + ((size_t)b * NC + r) * DQ + c4 * 4);
        Vst[(c4 * 4 + 0) * ES_PITCH + r] = v.x;
        Vst[(c4 * 4 + 1) * ES_PITCH + r] = v.y;
        Vst[(c4 * 4 + 2) * ES_PITCH + r] = v.z;
        Vst[(c4 * 4 + 3) * ES_PITCH + r] = v.w;
    }
    if (t < DQ) {
        Vst[t * ES_PITCH + 129] = 0.f;
        Es[t * ES_PITCH + 129]  = 0.f;
        float s = ZCONST * bv[t];
#pragma unroll
        for (int kg = 0; kg < 8; kg++) s += g_vtp[(b * 8 + kg) * DQ + t];
        Vt[t] = s;
    }
    __syncthreads();

    const int tx = t & 15, ty = t >> 4;

    ull acc2[4][12];
#pragma unroll
    for (int i = 0; i < 4; i++)
#pragma unroll
        for (int jj = 0; jj < 12; jj++) acc2[i][jj] = 0ull;

#pragma unroll 4
    for (int kp = 0; kp < 32; kp++) {
        ull qv[4], kv[12];
#pragma unroll
        for (int i = 0; i < 4; i++)
            qv[i] = *(const ull*)(Qs + (ty * 4 + i) * KS_PITCH + kp * 2);
#pragma unroll
        for (int jj = 0; jj < 12; jj++)
            kv[jj] = *(const ull*)(Ks + (tx + 16 * jj) * KS_PITCH + kp * 2);
#pragma unroll
        for (int i = 0; i < 4; i++)
#pragma unroll
            for (int jj = 0; jj < 12; jj++)
                ffma2(acc2[i][jj], qv[i], kv[jj]);
    }

#pragma unroll
    for (int i = 0; i < 4; i++) {
        int np = ty * 4 + i;
#pragma unroll
        for (int jj = 0; jj < 12; jj++) {
            int cc = tx + 16 * jj;
            int c = cc - np;
            if (c >= 0 && c < NC) {
                float lo = __uint_as_float((unsigned)acc2[i][jj]);
                float hi = __uint_as_float((unsigned)(acc2[i][jj] >> 32));
                Es[np * ES_PITCH + c] = expf(lo + hi);
            }
        }
    }
    __syncthreads();

    {
        const int w = t >> 5, lane = t & 31;
        for (int rr = 0; rr < 8; rr++) {
            int r = w * 8 + rr;
            float s = Es[r * ES_PITCH + lane] + Es[r * ES_PITCH + lane + 32]
                    + Es[r * ES_PITCH + lane + 64] + Es[r * ES_PITCH + lane + 96];
            if (lane == 0) s += Es[r * ES_PITCH + 128];
#pragma unroll
            for (int o = 16; o > 0; o >>= 1) s += __shfl_xor_sync(0xffffffffu, s, o);
            if (lane == 0) Zi[r] = 1.0f / (s + ZCONST);
        }
    }
    __syncthreads();

    ull oacc2[4][4];
#pragma unroll
    for (int i = 0; i < 4; i++)
#pragma unroll
        for (int i2 = 0; i2 < 4; i2++) oacc2[i][i2] = 0ull;

#pragma unroll 5
    for (int kp = 0; kp < 65; kp++) {
        ull ev[4], vv[4];
#pragma unroll
        for (int i = 0; i < 4; i++)
            ev[i] = *(const ull*)(Es + (ty * 4 + i) * ES_PITCH + kp * 2);
#pragma unroll
        for (int i2 = 0; i2 < 4; i2++)
            vv[i2] = *(const ull*)(Vst + (tx + 16 * i2) * ES_PITCH + kp * 2);
#pragma unroll
        for (int i = 0; i < 4; i++)
#pragma unroll
            for (int i2 = 0; i2 < 4; i2++)
                ffma2(oacc2[i][i2], ev[i], vv[i2]);
    }

#pragma unroll
    for (int i = 0; i < 4; i++) {
        int np = ty * 4 + i;
        float zi = Zi[np];
#pragma unroll
        for (int i2 = 0; i2 < 4; i2++) {
            int d = tx + 16 * i2;
            float lo = __uint_as_float((unsigned)oacc2[i][i2]);
            float hi = __uint_as_float((unsigned)(oacc2[i][i2] >> 32));
            out[((size_t)b * SEQ + n0 + np) * DQ + d] = (lo + hi + Vt[d]) * zi;
        }
    }
}

// ============================================================
// launcher
// ============================================================
extern "C" void kernel_launch(void* const* d_in, const int* in_sizes, int n_in,
                              void* d_out, int out_size) {
    const float* x  = (const float*)d_in[0];
    const float* Wq = (const float*)d_in[1];
    const float* bq = (const float*)d_in[2];
    const float* Wk = (const float*)d_in[3];
    const float* bk = (const float*)d_in[4];
    const float* Wv = (const float*)d_in[5];
    const float* bv = (const float*)d_in[6];
    float* out = (float*)d_out;

    cudaFuncSetAttribute(attn_kernel, cudaFuncAttributeMaxDynamicSharedMemorySize, SM_BYTES);

    prep_kernel<<<514, 128>>>(x, Wq, Wk, Wv, bv);
    vtail_combine_kernel<<<dim3(8, BATCH), 256>>>(Wv);
    proj_qk_kernel<<<dim3(SEQ / 32, BATCH), 256>>>(x, bq, bk);
    attn_kernel<<<dim3(SEQ / 64, BATCH), 256, SM_BYTES>>>(out, bv);
}

// round 7
// speedup vs baseline: 1.6007x; 1.6007x over previous
#include <cuda_runtime.h>
#include <math.h>

#define BATCH 2
#define SEQ   4096
#define EMB   512
#define DQ    64
#define NC    129
#define ZCONST 3967.0f

typedef unsigned long long ull;

// ---- scratch (allocation-free: device globals) ----
__device__ float g_Q[BATCH * SEQ * DQ];
__device__ float g_K[BATCH * SEQ * DQ];
__device__ float g_Vc[BATCH * NC * DQ];
__device__ float g_part[BATCH * 64 * EMB];
__device__ float g_vtp[BATCH * 8 * DQ];
// packed W, kp-major: g_Wp2[kp][d] = {wq[2kp],wq[2kp+1],wk[2kp],wk[2kp+1]}
__device__ float4 g_Wp2[256 * DQ];

__device__ __forceinline__ void ffma2(ull& acc, ull a, ull b) {
    asm("fma.rn.f32x2 %0, %1, %2, %0;" : "+l"(acc) : "l"(a), "l"(b));
}
__device__ __forceinline__ ull pack2(float lo, float hi) {
    return ((ull)__float_as_uint(hi) << 32) | (ull)__float_as_uint(lo);
}
__device__ __forceinline__ float lo32(ull v) { return __uint_as_float((unsigned)v); }
__device__ __forceinline__ float hi32(ull v) { return __uint_as_float((unsigned)(v >> 32)); }

// ============================================================
// Kernel A (prep): 514 blocks x 128 threads.
//  [0,128):   pack W into g_Wp2 (kp-major, d contiguous)
//  [128,256): xsum partials over rows 129..4095
//  [256,514): V projection rows 0..128
// ============================================================
__global__ void __launch_bounds__(128)
prep_kernel(const float* __restrict__ x,
            const float* __restrict__ Wq, const float* __restrict__ Wk,
            const float* __restrict__ Wv, const float* __restrict__ bv) {
    const int bid = blockIdx.x, t = threadIdx.x;

    if (bid < 128) {
        const int kp = bid * 2 + (t >> 6);
        const int d  = t & 63;
        float4 w;
        w.x = Wq[(size_t)(2 * kp)     * DQ + d];
        w.y = Wq[(size_t)(2 * kp + 1) * DQ + d];
        w.z = Wk[(size_t)(2 * kp)     * DQ + d];
        w.w = Wk[(size_t)(2 * kp + 1) * DQ + d];
        g_Wp2[kp * DQ + d] = w;
    } else if (bid < 256) {
        const int i = bid - 128;
        const int b = i >> 6, ci = i & 63;
        int r0 = 129 + ci * 62;
        int r1 = r0 + 62; if (r1 > SEQ) r1 = SEQ;
        const float* xb = x + (size_t)b * SEQ * EMB;
        float4 s = make_float4(0.f, 0.f, 0.f, 0.f);
#pragma unroll 4
        for (int r = r0; r < r1; r++) {
            float4 v = *(const float4*)(xb + (size_t)r * EMB + t * 4);
            s.x += v.x; s.y += v.y; s.z += v.z; s.w += v.w;
        }
        *(float4*)(g_part + (b * 64 + ci) * EMB + t * 4) = s;
    } else {
        const int i = bid - 256;
        const int b = i / NC, r = i % NC;
        __shared__ float xsh[EMB];
        __shared__ float red[2][DQ];
        const float* xr = x + ((size_t)b * SEQ + r) * EMB;
        ((float4*)xsh)[t] = ((const float4*)xr)[t];
        __syncthreads();
        const int d = t & 63, h = t >> 6;
        float acc = 0.f;
        const int kb = h * 256;
#pragma unroll 8
        for (int k = 0; k < 256; k++)
            acc = fmaf(xsh[kb + k], Wv[(size_t)(kb + k) * DQ + d], acc);
        red[h][d] = acc;
        __syncthreads();
        if (t < DQ)
            g_Vc[(b * NC + r) * DQ + t] = red[0][t] + red[1][t] + bv[t];
    }
}

// ============================================================
// Kernel B: vtail partials per k-group: grid (8, 2), 256 threads.
// ============================================================
__global__ void vtail_combine_kernel(const float* __restrict__ Wv) {
    const int kg = blockIdx.x, b = blockIdx.y, t = threadIdx.x;
    __shared__ float red[4][DQ];
    __shared__ float xsum64[DQ];
    __shared__ float p2[4][DQ];
    {
        const int kk = t & 63, g = t >> 6;
        float s = 0.f;
#pragma unroll
        for (int ci = g; ci < 64; ci += 4)
            s += g_part[(b * 64 + ci) * EMB + kg * 64 + kk];
        red[g][kk] = s;
    }
    __syncthreads();
    if (t < DQ) xsum64[t] = red[0][t] + red[1][t] + red[2][t] + red[3][t];
    __syncthreads();
    {
        const int d = t & 63, g2 = t >> 6;
        float acc = 0.f;
#pragma unroll
        for (int kk = g2 * 16; kk < g2 * 16 + 16; kk++)
            acc = fmaf(xsum64[kk], Wv[(size_t)(kg * 64 + kk) * DQ + d], acc);
        p2[g2][d] = acc;
    }
    __syncthreads();
    if (t < DQ)
        g_vtp[(b * 8 + kg) * DQ + t] = p2[0][t] + p2[1][t] + p2[2][t] + p2[3][t];
}

// ============================================================
// Kernel C: Q/K projection. 32-row tiles, grid (256,2)->512? no: (128,2).
// 256 threads: rg = t&7 (8 groups x 4 rows), dg = t>>3 (32 groups x 2 d).
// x staged as XOR-swizzled k-pairs: xs2[r][kp ^ (r>>2)], pitch 64 ull (512B).
//  -> x LDS.64 conflict-free, W LDG.128 broadcast-merged (<=4 sectors/warp).
// Body per kp: 2 LDG.128 + 4 LDS.64 + 16 FFMA2  (fma-pipe-bound).
// ============================================================
__global__ void __launch_bounds__(256, 3)
proj_qk_kernel(const float* __restrict__ x,
               const float* __restrict__ bq, const float* __restrict__ bk) {
    __shared__ ull xs2[32][64];     // 16 KB
    const int b  = blockIdx.y;
    const int n0 = blockIdx.x * 32;
    const int t  = threadIdx.x;
    const int rg = t & 7;           // row group: rows rg*4 .. rg*4+3
    const int dg = t >> 5 == 0 ? (t >> 3) : (t >> 3);  // 0..31, d = dg*2+j

    ull qa[4][2], ka[4][2];
#pragma unroll
    for (int i = 0; i < 4; i++)
#pragma unroll
        for (int j = 0; j < 2; j++) { qa[i][j] = 0ull; ka[i][j] = 0ull; }

    const float* xb = x + ((size_t)b * SEQ + n0) * EMB;

    for (int k0 = 0; k0 < EMB; k0 += 128) {
        __syncthreads();
        // stage 32x128 chunk as swizzled pairs; gmem reads fully coalesced
        for (int idx = t; idx < 32 * 32; idx += 256) {
            int r = idx >> 5, c = idx & 31;
            float4 v = *(const float4*)(xb + (size_t)r * EMB + k0 + c * 4);
            int sw = r >> 2;
            xs2[r][(2 * c) ^ sw]     = pack2(v.x, v.y);
            xs2[r][(2 * c + 1) ^ sw] = pack2(v.z, v.w);
        }
        __syncthreads();

        const int kpb = k0 >> 1;
#pragma unroll 4
        for (int kp = 0; kp < 64; kp++) {
            const ulonglong2* wrow =
                (const ulonglong2*)(g_Wp2 + (size_t)(kpb + kp) * DQ) + dg * 2;
            ulonglong2 w0 = wrow[0];
            ulonglong2 w1 = wrow[1];
            ull x2[4];
#pragma unroll
            for (int i = 0; i < 4; i++)
                x2[i] = xs2[rg * 4 + i][kp ^ rg];
#pragma unroll
            for (int i = 0; i < 4; i++) {
                ffma2(qa[i][0], x2[i], w0.x);
                ffma2(ka[i][0], x2[i], w0.y);
                ffma2(qa[i][1], x2[i], w1.x);
                ffma2(ka[i][1], x2[i], w1.y);
            }
        }
    }

#pragma unroll
    for (int j = 0; j < 2; j++) {
        int d = dg * 2 + j;
        float bqv = bq[d], bkv = bk[d];
#pragma unroll
        for (int i = 0; i < 4; i++) {
            int n = n0 + rg * 4 + i;
            g_Q[((size_t)b * SEQ + n) * DQ + d] = lo32(qa[i][j]) + hi32(qa[i][j]) + bqv;
            g_K[((size_t)b * SEQ + n) * DQ + d] = lo32(ka[i][j]) + hi32(ka[i][j]) + bkv;
        }
    }
}

// ============================================================
// Kernel D: attention core — R4 scalar form (the 82.7us config).
// ============================================================
#define KS_PITCH 65
#define ES_PITCH 132
#define SM_KS 0
#define SM_QS (192 * KS_PITCH)
#define SM_ES (SM_QS + 64 * KS_PITCH)
#define SM_VS (SM_ES + 64 * ES_PITCH)
#define SM_ZI (SM_VS + NC * KS_PITCH)
#define SM_VT (SM_ZI + 64)
#define SM_FLOATS (SM_VT + 64)
#define SM_BYTES (SM_FLOATS * 4)

__global__ void attn_kernel(float* __restrict__ out, const float* __restrict__ bv) {
    extern __shared__ float sm[];
    float* Ks = sm + SM_KS;
    float* Qs = sm + SM_QS;
    float* Es = sm + SM_ES;
    float* Vs = sm + SM_VS;
    float* Zi = sm + SM_ZI;
    float* Vt = sm + SM_VT;

    const int b = blockIdx.y, n0 = blockIdx.x * 64, t = threadIdx.x;

    const float* Kb = g_K + (size_t)b * SEQ * DQ;
    for (int idx = t; idx < 192 * 16; idx += 256) {
        int r = idx >> 4, c4 = idx & 15;
        int j = n0 - 64 + r;
        float4 v = (j >= 0 && j < SEQ) ? *(const float4*)(Kb + (size_t)j * DQ + c4 * 4)
                                       : make_float4(0.f, 0.f, 0.f, 0.f);
        Ks[r * KS_PITCH + c4 * 4 + 0] = v.x; Ks[r * KS_PITCH + c4 * 4 + 1] = v.y;
        Ks[r * KS_PITCH + c4 * 4 + 2] = v.z; Ks[r * KS_PITCH + c4 * 4 + 3] = v.w;
    }
    const float* Qb = g_Q + ((size_t)b * SEQ + n0) * DQ;
    for (int idx = t; idx < 64 * 16; idx += 256) {
        int r = idx >> 4, c4 = idx & 15;
        float4 v = *(const float4*)(Qb + (size_t)r * DQ + c4 * 4);
        Qs[r * KS_PITCH + c4 * 4 + 0] = v.x; Qs[r * KS_PITCH + c4 * 4 + 1] = v.y;
        Qs[r * KS_PITCH + c4 * 4 + 2] = v.z; Qs[r * KS_PITCH + c4 * 4 + 3] = v.w;
    }
    for (int idx = t; idx < NC * 16; idx += 256) {
        int r = idx >> 4, c4 = idx & 15;
        float4 v = *(const float4*)(g_Vc + ((size_t)b * NC + r) * DQ + c4 * 4);
        Vs[r * KS_PITCH + c4 * 4 + 0] = v.x; Vs[r * KS_PITCH + c4 * 4 + 1] = v.y;
        Vs[r * KS_PITCH + c4 * 4 + 2] = v.z; Vs[r * KS_PITCH + c4 * 4 + 3] = v.w;
    }
    if (t < DQ) {
        float s = ZCONST * bv[t];
#pragma unroll
        for (int kg = 0; kg < 8; kg++) s += g_vtp[(b * 8 + kg) * DQ + t];
        Vt[t] = s;
    }
    __syncthreads();

    const int tx = t & 15, ty = t >> 4;

    float acc[4][12];
#pragma unroll
    for (int i = 0; i < 4; i++)
#pragma unroll
        for (int jj = 0; jj < 12; jj++) acc[i][jj] = 0.f;

#pragma unroll 4
    for (int k = 0; k < DQ; k++) {
        float qv[4], kv[12];
#pragma unroll
        for (int i = 0; i < 4; i++)   qv[i]  = Qs[(ty * 4 + i) * KS_PITCH + k];
#pragma unroll
        for (int jj = 0; jj < 12; jj++) kv[jj] = Ks[(tx + 16 * jj) * KS_PITCH + k];
#pragma unroll
        for (int i = 0; i < 4; i++)
#pragma unroll
            for (int jj = 0; jj < 12; jj++)
                acc[i][jj] = fmaf(qv[i], kv[jj], acc[i][jj]);
    }

#pragma unroll
    for (int i = 0; i < 4; i++) {
        int np = ty * 4 + i;
#pragma unroll
        for (int jj = 0; jj < 12; jj++) {
            int cc = tx + 16 * jj;
            int c = cc - np;
            if (c >= 0 && c < NC)
                Es[np * ES_PITCH + c] = expf(acc[i][jj]);
        }
    }
    __syncthreads();

    {
        const int w = t >> 5, lane = t & 31;
        for (int rr = 0; rr < 8; rr++) {
            int r = w * 8 + rr;
            float s = Es[r * ES_PITCH + lane] + Es[r * ES_PITCH + lane + 32]
                    + Es[r * ES_PITCH + lane + 64] + Es[r * ES_PITCH + lane + 96];
            if (lane == 0) s += Es[r * ES_PITCH + 128];
#pragma unroll
            for (int o = 16; o > 0; o >>= 1) s += __shfl_xor_sync(0xffffffffu, s, o);
            if (lane == 0) Zi[r] = 1.0f / (s + ZCONST);
        }
    }
    __syncthreads();

    float oacc[4][4];
#pragma unroll
    for (int i = 0; i < 4; i++)
#pragma unroll
        for (int i2 = 0; i2 < 4; i2++) oacc[i][i2] = 0.f;

#pragma unroll 3
    for (int c = 0; c < NC; c++) {
        float ev[4], vv[4];
#pragma unroll
        for (int i = 0; i < 4; i++)  ev[i]  = Es[(ty * 4 + i) * ES_PITCH + c];
#pragma unroll
        for (int i2 = 0; i2 < 4; i2++) vv[i2] = Vs[c * KS_PITCH + tx + 16 * i2];
#pragma unroll
        for (int i = 0; i < 4; i++)
#pragma unroll
            for (int i2 = 0; i2 < 4; i2++)
                oacc[i][i2] = fmaf(ev[i], vv[i2], oacc[i][i2]);
    }

#pragma unroll
    for (int i = 0; i < 4; i++) {
        int np = ty * 4 + i;
        float zi = Zi[np];
#pragma unroll
        for (int i2 = 0; i2 < 4; i2++) {
            int d = tx + 16 * i2;
            out[((size_t)b * SEQ + n0 + np) * DQ + d] = (oacc[i][i2] + Vt[d]) * zi;
        }
    }
}

// ============================================================
// launcher
// ============================================================
extern "C" void kernel_launch(void* const* d_in, const int* in_sizes, int n_in,
                              void* d_out, int out_size) {
    const float* x  = (const float*)d_in[0];
    const float* Wq = (const float*)d_in[1];
    const float* bq = (const float*)d_in[2];
    const float* Wk = (const float*)d_in[3];
    const float* bk = (const float*)d_in[4];
    const float* Wv = (const float*)d_in[5];
    const float* bv = (const float*)d_in[6];
    float* out = (float*)d_out;

    cudaFuncSetAttribute(attn_kernel, cudaFuncAttributeMaxDynamicSharedMemorySize, SM_BYTES);

    prep_kernel<<<514, 128>>>(x, Wq, Wk, Wv, bv);
    vtail_combine_kernel<<<dim3(8, BATCH), 256>>>(Wv);
    proj_qk_kernel<<<dim3(SEQ / 32, BATCH), 256>>>(x, bq, bk);
    attn_kernel<<<dim3(SEQ / 64, BATCH), 256, SM_BYTES>>>(out, bv);
}

// round 9
// speedup vs baseline: 1.6749x; 1.0464x over previous
#include <cuda_runtime.h>
#include <math.h>

#define BATCH 2
#define SEQ   4096
#define EMB   512
#define DQ    64
#define NC    129
#define ZCONST 3967.0f

typedef unsigned long long ull;

// ---- scratch (allocation-free: device globals) ----
__device__ float g_Q[BATCH * SEQ * DQ];
__device__ float g_K[BATCH * SEQ * DQ];
__device__ float g_Vc[BATCH * NC * DQ];
__device__ float g_part[BATCH * 64 * EMB];
__device__ float g_vtp[BATCH * 8 * DQ];
__device__ float4 g_Wp2[256 * DQ];   // [kp][d]: {wq2kp, wq2kp+1, wk2kp, wk2kp+1}

__device__ __forceinline__ void ffma2(ull& acc, ull a, ull b) {
    asm("fma.rn.f32x2 %0, %1, %2, %0;" : "+l"(acc) : "l"(a), "l"(b));
}
__device__ __forceinline__ ull pack2(float lo, float hi) {
    return ((ull)__float_as_uint(hi) << 32) | (ull)__float_as_uint(lo);
}
__device__ __forceinline__ float lo32(ull v) { return __uint_as_float((unsigned)v); }
__device__ __forceinline__ float hi32(ull v) { return __uint_as_float((unsigned)(v >> 32)); }

// ============================================================
// Kernel A (prep): 514 blocks x 128 threads.
// ============================================================
__global__ void __launch_bounds__(128)
prep_kernel(const float* __restrict__ x,
            const float* __restrict__ Wq, const float* __restrict__ Wk,
            const float* __restrict__ Wv, const float* __restrict__ bv) {
    const int bid = blockIdx.x, t = threadIdx.x;

    if (bid < 128) {
        const int kp = bid * 2 + (t >> 6);
        const int d  = t & 63;
        float4 w;
        w.x = Wq[(size_t)(2 * kp)     * DQ + d];
        w.y = Wq[(size_t)(2 * kp + 1) * DQ + d];
        w.z = Wk[(size_t)(2 * kp)     * DQ + d];
        w.w = Wk[(size_t)(2 * kp + 1) * DQ + d];
        g_Wp2[kp * DQ + d] = w;
    } else if (bid < 256) {
        const int i = bid - 128;
        const int b = i >> 6, ci = i & 63;
        int r0 = 129 + ci * 62;
        int r1 = r0 + 62; if (r1 > SEQ) r1 = SEQ;
        const float* xb = x + (size_t)b * SEQ * EMB;
        float4 s = make_float4(0.f, 0.f, 0.f, 0.f);
#pragma unroll 4
        for (int r = r0; r < r1; r++) {
            float4 v = *(const float4*)(xb + (size_t)r * EMB + t * 4);
            s.x += v.x; s.y += v.y; s.z += v.z; s.w += v.w;
        }
        *(float4*)(g_part + (b * 64 + ci) * EMB + t * 4) = s;
    } else {
        const int i = bid - 256;
        const int b = i / NC, r = i % NC;
        __shared__ float xsh[EMB];
        __shared__ float red[2][DQ];
        const float* xr = x + ((size_t)b * SEQ + r) * EMB;
        ((float4*)xsh)[t] = ((const float4*)xr)[t];
        __syncthreads();
        const int d = t & 63, h = t >> 6;
        float acc = 0.f;
        const int kb = h * 256;
#pragma unroll 8
        for (int k = 0; k < 256; k++)
            acc = fmaf(xsh[kb + k], Wv[(size_t)(kb + k) * DQ + d], acc);
        red[h][d] = acc;
        __syncthreads();
        if (t < DQ)
            g_Vc[(b * NC + r) * DQ + t] = red[0][t] + red[1][t] + bv[t];
    }
}

// ============================================================
// Kernel B: vtail partials per k-group: grid (8, 2), 256 threads.
// ============================================================
__global__ void vtail_combine_kernel(const float* __restrict__ Wv) {
    const int kg = blockIdx.x, b = blockIdx.y, t = threadIdx.x;
    __shared__ float red[4][DQ];
    __shared__ float xsum64[DQ];
    __shared__ float p2[4][DQ];
    {
        const int kk = t & 63, g = t >> 6;
        float s = 0.f;
#pragma unroll
        for (int ci = g; ci < 64; ci += 4)
            s += g_part[(b * 64 + ci) * EMB + kg * 64 + kk];
        red[g][kk] = s;
    }
    __syncthreads();
    if (t < DQ) xsum64[t] = red[0][t] + red[1][t] + red[2][t] + red[3][t];
    __syncthreads();
    {
        const int d = t & 63, g2 = t >> 6;
        float acc = 0.f;
#pragma unroll
        for (int kk = g2 * 16; kk < g2 * 16 + 16; kk++)
            acc = fmaf(xsum64[kk], Wv[(size_t)(kg * 64 + kk) * DQ + d], acc);
        p2[g2][d] = acc;
    }
    __syncthreads();
    if (t < DQ)
        g_vtp[(b * 8 + kg) * DQ + t] = p2[0][t] + p2[1][t] + p2[2][t] + p2[3][t];
}

// ============================================================
// Kernel C: Q/K projection (R7 config, unchanged).
// ============================================================
__global__ void __launch_bounds__(256, 3)
proj_qk_kernel(const float* __restrict__ x,
               const float* __restrict__ bq, const float* __restrict__ bk) {
    __shared__ ull xs2[32][64];
    const int b  = blockIdx.y;
    const int n0 = blockIdx.x * 32;
    const int t  = threadIdx.x;
    const int rg = t & 7;
    const int dg = t >> 3;

    ull qa[4][2], ka[4][2];
#pragma unroll
    for (int i = 0; i < 4; i++)
#pragma unroll
        for (int j = 0; j < 2; j++) { qa[i][j] = 0ull; ka[i][j] = 0ull; }

    const float* xb = x + ((size_t)b * SEQ + n0) * EMB;

    for (int k0 = 0; k0 < EMB; k0 += 128) {
        __syncthreads();
        for (int idx = t; idx < 32 * 32; idx += 256) {
            int r = idx >> 5, c = idx & 31;
            float4 v = *(const float4*)(xb + (size_t)r * EMB + k0 + c * 4);
            int sw = r >> 2;
            xs2[r][(2 * c) ^ sw]     = pack2(v.x, v.y);
            xs2[r][(2 * c + 1) ^ sw] = pack2(v.z, v.w);
        }
        __syncthreads();

        const int kpb = k0 >> 1;
#pragma unroll 4
        for (int kp = 0; kp < 64; kp++) {
            const ulonglong2* wrow =
                (const ulonglong2*)(g_Wp2 + (size_t)(kpb + kp) * DQ) + dg * 2;
            ulonglong2 w0 = wrow[0];
            ulonglong2 w1 = wrow[1];
            ull x2[4];
#pragma unroll
            for (int i = 0; i < 4; i++)
                x2[i] = xs2[rg * 4 + i][kp ^ rg];
#pragma unroll
            for (int i = 0; i < 4; i++) {
                ffma2(qa[i][0], x2[i], w0.x);
                ffma2(ka[i][0], x2[i], w0.y);
                ffma2(qa[i][1], x2[i], w1.x);
                ffma2(ka[i][1], x2[i], w1.y);
            }
        }
    }

#pragma unroll
    for (int j = 0; j < 2; j++) {
        int d = dg * 2 + j;
        float bqv = bq[d], bkv = bk[d];
#pragma unroll
        for (int i = 0; i < 4; i++) {
            int n = n0 + rg * 4 + i;
            g_Q[((size_t)b * SEQ + n) * DQ + d] = lo32(qa[i][j]) + hi32(qa[i][j]) + bqv;
            g_K[((size_t)b * SEQ + n) * DQ + d] = lo32(ka[i][j]) + hi32(ka[i][j]) + bkv;
        }
    }
}

// ============================================================
// Kernel D: attention core. 32-row tiles, 256 threads, smem overlay.
//  Ks region (160x65) reused for Es (32x132) after phase 1.
//  smem 83.8KB -> 2 blocks/SM; grid (128,2)=256 blocks, all resident.
// ============================================================
#define KROWS 160               // 32 + 128 window
#define AP    65                // K/Q/V pitch
#define EP    132               // Es pitch
#define AKS   0                 // Ks 160*65=10400; overlaid Es 32*132=4224
#define AQS   10400             // Qs 32*65 = 2080
#define AVS   12480             // Vs 129*65 = 8385
#define AZI   20865             // 32
#define AVT   20897             // 64
#define A_FLOATS 20961
#define A_BYTES (A_FLOATS * 4)

__global__ void __launch_bounds__(256, 2)
attn_kernel(float* __restrict__ out, const float* __restrict__ bv) {
    extern __shared__ float sm[];
    float* Ks = sm + AKS;
    float* Es = sm + AKS;      // overlay after phase 1
    float* Qs = sm + AQS;
    float* Vs = sm + AVS;
    float* Zi = sm + AZI;
    float* Vt = sm + AVT;

    const int b = blockIdx.y, n0 = blockIdx.x * 32, t = threadIdx.x;

    // --- stage K window (160 rows, zero-padded), Q tile, V, Vtail ---
    const float* Kb = g_K + (size_t)b * SEQ * DQ;
    for (int idx = t; idx < KROWS * 16; idx += 256) {
        int r = idx >> 4, c4 = idx & 15;
        int j = n0 - 64 + r;
        float4 v = (j >= 0 && j < SEQ) ? *(const float4*)(Kb + (size_t)j * DQ + c4 * 4)
                                       : make_float4(0.f, 0.f, 0.f, 0.f);
        float* p = Ks + r * AP + c4 * 4;
        p[0] = v.x; p[1] = v.y; p[2] = v.z; p[3] = v.w;
    }
    const float* Qb = g_Q + ((size_t)b * SEQ + n0) * DQ;
    for (int idx = t; idx < 32 * 16; idx += 256) {
        int r = idx >> 4, c4 = idx & 15;
        float4 v = *(const float4*)(Qb + (size_t)r * DQ + c4 * 4);
        float* p = Qs + r * AP + c4 * 4;
        p[0] = v.x; p[1] = v.y; p[2] = v.z; p[3] = v.w;
    }
    for (int idx = t; idx < NC * 16; idx += 256) {
        int r = idx >> 4, c4 = idx & 15;
        float4 v = *(const float4*)(g_Vc + ((size_t)b * NC + r) * DQ + c4 * 4);
        float* p = Vs + r * AP + c4 * 4;
        p[0] = v.x; p[1] = v.y; p[2] = v.z; p[3] = v.w;
    }
    if (t < DQ) {
        float s = ZCONST * bv[t];
#pragma unroll
        for (int kg = 0; kg < 8; kg++) s += g_vtp[(b * 8 + kg) * DQ + t];
        Vt[t] = s;
    }
    __syncthreads();

    const int tx = t & 31, ty = t >> 5;   // ty 0..7 -> rows ty*4..ty*4+3

    // --- phase 1: S(32x160) = Q * Ks^T, thread tile 4 rows x 5 cols ---
    float acc[4][5];
#pragma unroll
    for (int i = 0; i < 4; i++)
#pragma unroll
        for (int jj = 0; jj < 5; jj++) acc[i][jj] = 0.f;

#pragma unroll 8
    for (int k = 0; k < DQ; k++) {
        float qv[4], kv[5];
#pragma unroll
        for (int i = 0; i < 4; i++)  qv[i]  = Qs[(ty * 4 + i) * AP + k];
#pragma unroll
        for (int jj = 0; jj < 5; jj++) kv[jj] = Ks[(tx + 32 * jj) * AP + k];
#pragma unroll
        for (int i = 0; i < 4; i++)
#pragma unroll
            for (int jj = 0; jj < 5; jj++)
                acc[i][jj] = fmaf(qv[i], kv[jj], acc[i][jj]);
    }
    __syncthreads();   // all Ks reads done before Es overlay writes

    // --- phase 1.5: exp + scatter into Es[row][c], c = cc - np ---
#pragma unroll
    for (int i = 0; i < 4; i++) {
        int np = ty * 4 + i;
#pragma unroll
        for (int jj = 0; jj < 5; jj++) {
            int cc = tx + 32 * jj;
            int c = cc - np;
            if (c >= 0 && c < NC)
                Es[np * EP + c] = expf(acc[i][jj]);
        }
    }
    __syncthreads();

    // --- Z per row: 8 warps x 4 rows ---
    {
        const int w = ty, lane = tx;
#pragma unroll
        for (int rr = 0; rr < 4; rr++) {
            int r = w * 4 + rr;
            float s = Es[r * EP + lane] + Es[r * EP + lane + 32]
                    + Es[r * EP + lane + 64] + Es[r * EP + lane + 96];
            if (lane == 0) s += Es[r * EP + 128];
#pragma unroll
            for (int o = 16; o > 0; o >>= 1) s += __shfl_xor_sync(0xffffffffu, s, o);
            if (lane == 0) Zi[r] = 1.0f / (s + ZCONST);
        }
    }
    __syncthreads();

    // --- phase 2: O(32x64) = E(32x129) * Vs, thread tile 4 rows x 2 cols ---
    float oacc[4][2];
#pragma unroll
    for (int i = 0; i < 4; i++) { oacc[i][0] = 0.f; oacc[i][1] = 0.f; }

#pragma unroll 3
    for (int c = 0; c < NC; c++) {
        float ev[4], vv[2];
#pragma unroll
        for (int i = 0; i < 4; i++) ev[i] = Es[(ty * 4 + i) * EP + c];
        vv[0] = Vs[c * AP + tx];
        vv[1] = Vs[c * AP + tx + 32];
#pragma unroll
        for (int i = 0; i < 4; i++) {
            oacc[i][0] = fmaf(ev[i], vv[0], oacc[i][0]);
            oacc[i][1] = fmaf(ev[i], vv[1], oacc[i][1]);
        }
    }

#pragma unroll
    for (int i = 0; i < 4; i++) {
        int np = ty * 4 + i;
        float zi = Zi[np];
        int d0 = tx, d1 = tx + 32;
        out[((size_t)b * SEQ + n0 + np) * DQ + d0] = (oacc[i][0] + Vt[d0]) * zi;
        out[((size_t)b * SEQ + n0 + np) * DQ + d1] = (oacc[i][1] + Vt[d1]) * zi;
    }
}

// ============================================================
// launcher
// ============================================================
extern "C" void kernel_launch(void* const* d_in, const int* in_sizes, int n_in,
                              void* d_out, int out_size) {
    const float* x  = (const float*)d_in[0];
    const float* Wq = (const float*)d_in[1];
    const float* bq = (const float*)d_in[2];
    const float* Wk = (const float*)d_in[3];
    const float* bk = (const float*)d_in[4];
    const float* Wv = (const float*)d_in[5];
    const float* bv = (const float*)d_in[6];
    float* out = (float*)d_out;

    cudaFuncSetAttribute(attn_kernel, cudaFuncAttributeMaxDynamicSharedMemorySize, A_BYTES);

    prep_kernel<<<514, 128>>>(x, Wq, Wk, Wv, bv);
    vtail_combine_kernel<<<dim3(8, BATCH), 256>>>(Wv);
    proj_qk_kernel<<<dim3(SEQ / 32, BATCH), 256>>>(x, bq, bk);
    attn_kernel<<<dim3(SEQ / 32, BATCH), 256, A_BYTES>>>(out, bv);
}

// round 10
// speedup vs baseline: 1.7307x; 1.0333x over previous
#include <cuda_runtime.h>
#include <math.h>

#define BATCH 2
#define SEQ   4096
#define EMB   512
#define DQ    64
#define NC    129
#define ZCONST 3967.0f

typedef unsigned long long ull;

// ---- scratch (allocation-free: device globals) ----
__device__ float g_Q[BATCH * SEQ * DQ];
__device__ float g_K[BATCH * SEQ * DQ];
__device__ float g_Vc[BATCH * NC * DQ];
__device__ float g_part[BATCH * 64 * EMB];
__device__ float g_vtp[BATCH * 8 * DQ];
__device__ float4 g_Wp2[256 * DQ];   // [kp][d]: {wq2kp, wq2kp+1, wk2kp, wk2kp+1}

__device__ __forceinline__ void ffma2(ull& acc, ull a, ull b) {
    asm("fma.rn.f32x2 %0, %1, %2, %0;" : "+l"(acc) : "l"(a), "l"(b));
}
__device__ __forceinline__ ull pack2(float lo, float hi) {
    return ((ull)__float_as_uint(hi) << 32) | (ull)__float_as_uint(lo);
}
__device__ __forceinline__ float lo32(ull v) { return __uint_as_float((unsigned)v); }
__device__ __forceinline__ float hi32(ull v) { return __uint_as_float((unsigned)(v >> 32)); }

// ============================================================
// Kernel A (prep): 514 blocks x 128 threads. (unchanged)
// ============================================================
__global__ void __launch_bounds__(128)
prep_kernel(const float* __restrict__ x,
            const float* __restrict__ Wq, const float* __restrict__ Wk,
            const float* __restrict__ Wv, const float* __restrict__ bv) {
    const int bid = blockIdx.x, t = threadIdx.x;

    if (bid < 128) {
        const int kp = bid * 2 + (t >> 6);
        const int d  = t & 63;
        float4 w;
        w.x = Wq[(size_t)(2 * kp)     * DQ + d];
        w.y = Wq[(size_t)(2 * kp + 1) * DQ + d];
        w.z = Wk[(size_t)(2 * kp)     * DQ + d];
        w.w = Wk[(size_t)(2 * kp + 1) * DQ + d];
        g_Wp2[kp * DQ + d] = w;
    } else if (bid < 256) {
        const int i = bid - 128;
        const int b = i >> 6, ci = i & 63;
        int r0 = 129 + ci * 62;
        int r1 = r0 + 62; if (r1 > SEQ) r1 = SEQ;
        const float* xb = x + (size_t)b * SEQ * EMB;
        float4 s = make_float4(0.f, 0.f, 0.f, 0.f);
#pragma unroll 4
        for (int r = r0; r < r1; r++) {
            float4 v = *(const float4*)(xb + (size_t)r * EMB + t * 4);
            s.x += v.x; s.y += v.y; s.z += v.z; s.w += v.w;
        }
        *(float4*)(g_part + (b * 64 + ci) * EMB + t * 4) = s;
    } else {
        const int i = bid - 256;
        const int b = i / NC, r = i % NC;
        __shared__ float xsh[EMB];
        __shared__ float red[2][DQ];
        const float* xr = x + ((size_t)b * SEQ + r) * EMB;
        ((float4*)xsh)[t] = ((const float4*)xr)[t];
        __syncthreads();
        const int d = t & 63, h = t >> 6;
        float acc = 0.f;
        const int kb = h * 256;
#pragma unroll 8
        for (int k = 0; k < 256; k++)
            acc = fmaf(xsh[kb + k], Wv[(size_t)(kb + k) * DQ + d], acc);
        red[h][d] = acc;
        __syncthreads();
        if (t < DQ)
            g_Vc[(b * NC + r) * DQ + t] = red[0][t] + red[1][t] + bv[t];
    }
}

// ============================================================
// Kernel B: vtail partials per k-group: grid (8, 2), 256 threads. (unchanged)
// ============================================================
__global__ void vtail_combine_kernel(const float* __restrict__ Wv) {
    const int kg = blockIdx.x, b = blockIdx.y, t = threadIdx.x;
    __shared__ float red[4][DQ];
    __shared__ float xsum64[DQ];
    __shared__ float p2[4][DQ];
    {
        const int kk = t & 63, g = t >> 6;
        float s = 0.f;
#pragma unroll
        for (int ci = g; ci < 64; ci += 4)
            s += g_part[(b * 64 + ci) * EMB + kg * 64 + kk];
        red[g][kk] = s;
    }
    __syncthreads();
    if (t < DQ) xsum64[t] = red[0][t] + red[1][t] + red[2][t] + red[3][t];
    __syncthreads();
    {
        const int d = t & 63, g2 = t >> 6;
        float acc = 0.f;
#pragma unroll
        for (int kk = g2 * 16; kk < g2 * 16 + 16; kk++)
            acc = fmaf(xsum64[kk], Wv[(size_t)(kg * 64 + kk) * DQ + d], acc);
        p2[g2][d] = acc;
    }
    __syncthreads();
    if (t < DQ)
        g_vtp[(b * 8 + kg) * DQ + t] = p2[0][t] + p2[1][t] + p2[2][t] + p2[3][t];
}

// ============================================================
// Kernel C: Q/K projection (R7 config, unchanged).
// ============================================================
__global__ void __launch_bounds__(256, 3)
proj_qk_kernel(const float* __restrict__ x,
               const float* __restrict__ bq, const float* __restrict__ bk) {
    __shared__ ull xs2[32][64];
    const int b  = blockIdx.y;
    const int n0 = blockIdx.x * 32;
    const int t  = threadIdx.x;
    const int rg = t & 7;
    const int dg = t >> 3;

    ull qa[4][2], ka[4][2];
#pragma unroll
    for (int i = 0; i < 4; i++)
#pragma unroll
        for (int j = 0; j < 2; j++) { qa[i][j] = 0ull; ka[i][j] = 0ull; }

    const float* xb = x + ((size_t)b * SEQ + n0) * EMB;

    for (int k0 = 0; k0 < EMB; k0 += 128) {
        __syncthreads();
        for (int idx = t; idx < 32 * 32; idx += 256) {
            int r = idx >> 5, c = idx & 31;
            float4 v = *(const float4*)(xb + (size_t)r * EMB + k0 + c * 4);
            int sw = r >> 2;
            xs2[r][(2 * c) ^ sw]     = pack2(v.x, v.y);
            xs2[r][(2 * c + 1) ^ sw] = pack2(v.z, v.w);
        }
        __syncthreads();

        const int kpb = k0 >> 1;
#pragma unroll 4
        for (int kp = 0; kp < 64; kp++) {
            const ulonglong2* wrow =
                (const ulonglong2*)(g_Wp2 + (size_t)(kpb + kp) * DQ) + dg * 2;
            ulonglong2 w0 = wrow[0];
            ulonglong2 w1 = wrow[1];
            ull x2[4];
#pragma unroll
            for (int i = 0; i < 4; i++)
                x2[i] = xs2[rg * 4 + i][kp ^ rg];
#pragma unroll
            for (int i = 0; i < 4; i++) {
                ffma2(qa[i][0], x2[i], w0.x);
                ffma2(ka[i][0], x2[i], w0.y);
                ffma2(qa[i][1], x2[i], w1.x);
                ffma2(ka[i][1], x2[i], w1.y);
            }
        }
    }

#pragma unroll
    for (int j = 0; j < 2; j++) {
        int d = dg * 2 + j;
        float bqv = bq[d], bkv = bk[d];
#pragma unroll
        for (int i = 0; i < 4; i++) {
            int n = n0 + rg * 4 + i;
            g_Q[((size_t)b * SEQ + n) * DQ + d] = lo32(qa[i][j]) + hi32(qa[i][j]) + bqv;
            g_K[((size_t)b * SEQ + n) * DQ + d] = lo32(ka[i][j]) + hi32(ka[i][j]) + bkv;
        }
    }
}

// ============================================================
// Kernel D: attention core, 32-row tiles, FFMA2 both GEMM phases.
//  Pitches: Ks/Qs 66 (33x8B rows -> conflict-free LDS.64),
//           Es/Vst 130 (65x8B rows -> conflict-free), c=129 zero-padded.
//  Es overlays Ks after phase 1. smem ~84.4KB -> 2 blocks/SM.
// ============================================================
#define KROWS 160
#define AP    66                // K/Q pitch (even)
#define EP    130               // Es / Vst pitch (even)
#define AKS   0                 // Ks 160*66 = 10560 ; Es overlay 32*130 = 4160
#define AQS   10560             // Qs 32*66 = 2112
#define AVS   12672             // Vst 64*130 = 8320
#define AZI   20992             // 32
#define AVT   21024             // 64
#define A_FLOATS 21088
#define A_BYTES (A_FLOATS * 4)

__global__ void __launch_bounds__(256, 2)
attn_kernel(float* __restrict__ out, const float* __restrict__ bv) {
    extern __shared__ float sm[];
    float* Ks  = sm + AKS;
    float* Es  = sm + AKS;      // overlay after phase 1
    float* Qs  = sm + AQS;
    float* Vst = sm + AVS;      // transposed V: Vst[d][c]
    float* Zi  = sm + AZI;
    float* Vt  = sm + AVT;

    const int b = blockIdx.y, n0 = blockIdx.x * 32, t = threadIdx.x;

    // --- stage K window (160 rows, zero-padded) ---
    const float* Kb = g_K + (size_t)b * SEQ * DQ;
    for (int idx = t; idx < KROWS * 16; idx += 256) {
        int r = idx >> 4, c4 = idx & 15;
        int j = n0 - 64 + r;
        float4 v = (j >= 0 && j < SEQ) ? *(const float4*)(Kb + (size_t)j * DQ + c4 * 4)
                                       : make_float4(0.f, 0.f, 0.f, 0.f);
        float* p = Ks + r * AP + c4 * 4;
        p[0] = v.x; p[1] = v.y; p[2] = v.z; p[3] = v.w;
    }
    // --- stage Q tile ---
    const float* Qb = g_Q + ((size_t)b * SEQ + n0) * DQ;
    for (int idx = t; idx < 32 * 16; idx += 256) {
        int r = idx >> 4, c4 = idx & 15;
        float4 v = *(const float4*)(Qb + (size_t)r * DQ + c4 * 4);
        float* p = Qs + r * AP + c4 * 4;
        p[0] = v.x; p[1] = v.y; p[2] = v.z; p[3] = v.w;
    }
    // --- stage V transposed: Vst[d][c] = Vc[c][d]; pad c=129 ---
    for (int idx = t; idx < NC * 16; idx += 256) {
        int r = idx >> 4, c4 = idx & 15;     // r = c index, c4*4.. = d
        float4 v = *(const float4*)(g_Vc + ((size_t)b * NC + r) * DQ + c4 * 4);
        Vst[(c4 * 4 + 0) * EP + r] = v.x;
        Vst[(c4 * 4 + 1) * EP + r] = v.y;
        Vst[(c4 * 4 + 2) * EP + r] = v.z;
        Vst[(c4 * 4 + 3) * EP + r] = v.w;
    }
    if (t < DQ) {
        Vst[t * EP + 129] = 0.f;
        float s = ZCONST * bv[t];
#pragma unroll
        for (int kg = 0; kg < 8; kg++) s += g_vtp[(b * 8 + kg) * DQ + t];
        Vt[t] = s;
    }
    __syncthreads();

    const int tx = t & 31, ty = t >> 5;   // ty 0..7 -> rows ty*4..ty*4+3

    // --- phase 1: S(32x160) = Q * Ks^T, FFMA2 k-pairs, tile 4 rows x 5 cols ---
    ull acc2[4][5];
#pragma unroll
    for (int i = 0; i < 4; i++)
#pragma unroll
        for (int jj = 0; jj < 5; jj++) acc2[i][jj] = 0ull;

#pragma unroll 8
    for (int kp = 0; kp < 32; kp++) {
        ull qv[4], kv[5];
#pragma unroll
        for (int i = 0; i < 4; i++)
            qv[i] = *(const ull*)(Qs + (ty * 4 + i) * AP + kp * 2);
#pragma unroll
        for (int jj = 0; jj < 5; jj++)
            kv[jj] = *(const ull*)(Ks + (tx + 32 * jj) * AP + kp * 2);
#pragma unroll
        for (int i = 0; i < 4; i++)
#pragma unroll
            for (int jj = 0; jj < 5; jj++)
                ffma2(acc2[i][jj], qv[i], kv[jj]);
    }
    __syncthreads();   // all Ks reads done before Es overlay writes

    // --- phase 1.5: exp + scatter into Es[row][c], c = cc - np ---
#pragma unroll
    for (int i = 0; i < 4; i++) {
        int np = ty * 4 + i;
#pragma unroll
        for (int jj = 0; jj < 5; jj++) {
            int cc = tx + 32 * jj;
            int c = cc - np;
            if (c >= 0 && c < NC)
                Es[np * EP + c] = expf(lo32(acc2[i][jj]) + hi32(acc2[i][jj]));
        }
    }
    // zero-pad Es c=129 (one lane per row)
    if (t < 32) Es[t * EP + 129] = 0.f;
    __syncthreads();

    // --- Z per row: 8 warps x 4 rows ---
    {
        const int w = ty, lane = tx;
#pragma unroll
        for (int rr = 0; rr < 4; rr++) {
            int r = w * 4 + rr;
            float s = Es[r * EP + lane] + Es[r * EP + lane + 32]
                    + Es[r * EP + lane + 64] + Es[r * EP + lane + 96];
            if (lane == 0) s += Es[r * EP + 128];
#pragma unroll
            for (int o = 16; o > 0; o >>= 1) s += __shfl_xor_sync(0xffffffffu, s, o);
            if (lane == 0) Zi[r] = 1.0f / (s + ZCONST);
        }
    }
    __syncthreads();

    // --- phase 2: O(32x64) = E * V^T, FFMA2 c-pairs (65), tile 4 rows x 2 d ---
    ull oacc2[4][2];
#pragma unroll
    for (int i = 0; i < 4; i++) { oacc2[i][0] = 0ull; oacc2[i][1] = 0ull; }

#pragma unroll 5
    for (int kp = 0; kp < 65; kp++) {
        ull ev[4], vv[2];
#pragma unroll
        for (int i = 0; i < 4; i++)
            ev[i] = *(const ull*)(Es + (ty * 4 + i) * EP + kp * 2);
        vv[0] = *(const ull*)(Vst + tx * EP + kp * 2);
        vv[1] = *(const ull*)(Vst + (tx + 32) * EP + kp * 2);
#pragma unroll
        for (int i = 0; i < 4; i++) {
            ffma2(oacc2[i][0], ev[i], vv[0]);
            ffma2(oacc2[i][1], ev[i], vv[1]);
        }
    }

#pragma unroll
    for (int i = 0; i < 4; i++) {
        int np = ty * 4 + i;
        float zi = Zi[np];
        int d0 = tx, d1 = tx + 32;
        out[((size_t)b * SEQ + n0 + np) * DQ + d0] =
            (lo32(oacc2[i][0]) + hi32(oacc2[i][0]) + Vt[d0]) * zi;
        out[((size_t)b * SEQ + n0 + np) * DQ + d1] =
            (lo32(oacc2[i][1]) + hi32(oacc2[i][1]) + Vt[d1]) * zi;
    }
}

// ============================================================
// launcher
// ============================================================
extern "C" void kernel_launch(void* const* d_in, const int* in_sizes, int n_in,
                              void* d_out, int out_size) {
    const float* x  = (const float*)d_in[0];
    const float* Wq = (const float*)d_in[1];
    const float* bq = (const float*)d_in[2];
    const float* Wk = (const float*)d_in[3];
    const float* bk = (const float*)d_in[4];
    const float* Wv = (const float*)d_in[5];
    const float* bv = (const float*)d_in[6];
    float* out = (float*)d_out;

    cudaFuncSetAttribute(attn_kernel, cudaFuncAttributeMaxDynamicSharedMemorySize, A_BYTES);

    prep_kernel<<<514, 128>>>(x, Wq, Wk, Wv, bv);
    vtail_combine_kernel<<<dim3(8, BATCH), 256>>>(Wv);
    proj_qk_kernel<<<dim3(SEQ / 32, BATCH), 256>>>(x, bq, bk);
    attn_kernel<<<dim3(SEQ / 32, BATCH), 256, A_BYTES>>>(out, bv);
}